// round 1
// baseline (speedup 1.0000x reference)
#include <cuda_runtime.h>

#define BATCH 128
#define NTF 1024
#define NGENES 20000
#define CHUNK 32                 // batch elements per block (feature slice in smem)
#define NCHUNK 4                 // 128 / 32
#define THREADS 512              // 16 warps
#define GENES_PER_TILE 64        // 16 warps * 4 genes
#define NTILES ((NGENES + GENES_PER_TILE - 1) / GENES_PER_TILE)  // 313
#define SMEM_BYTES (NTF * CHUNK * 4)  // 131072

// scratch: transposed features [NTF][BATCH], and per-chunk work tickets
__device__ float g_xT[NTF * BATCH];
__device__ unsigned int g_ticket[NCHUNK];

// features [BATCH][NTF] -> g_xT [NTF][BATCH]; also reset tickets
__global__ void transpose_kernel(const float* __restrict__ f) {
    __shared__ float tile[32][33];
    const int tx = threadIdx.x, ty = threadIdx.y;
    const int t0 = blockIdx.x * 32;   // TF base
    const int b0 = blockIdx.y * 32;   // batch base
#pragma unroll
    for (int j = 0; j < 32; j += 8)
        tile[ty + j][tx] = f[(b0 + ty + j) * NTF + t0 + tx];
    __syncthreads();
#pragma unroll
    for (int j = 0; j < 32; j += 8)
        g_xT[(t0 + ty + j) * BATCH + b0 + tx] = tile[tx][ty + j];
    if (blockIdx.x == 0 && blockIdx.y == 0 && ty == 0 && tx < NCHUNK)
        g_ticket[tx] = 0u;
}

__device__ __forceinline__ float4 fma4(float s, float4 f, float4 a) {
    a.x += s * f.x; a.y += s * f.y; a.z += s * f.z; a.w += s * f.w;
    return a;
}

__device__ __forceinline__ float4 tanh4(float4 a, float b) {
    return make_float4(tanhf(a.x + b), tanhf(a.y + b),
                       tanhf(a.z + b), tanhf(a.w + b));
}

__device__ __forceinline__ float comp(float4 v, int i) {
    return (i == 0) ? v.x : (i == 1) ? v.y : (i == 2) ? v.z : v.w;
}

__global__ void __launch_bounds__(THREADS, 1) fused_kernel(
    const float* __restrict__ w1, const float* __restrict__ b1,
    const float* __restrict__ w2, const float* __restrict__ b2,
    const float* __restrict__ w3, const float* __restrict__ b3,
    const int*   __restrict__ in1,
    float* __restrict__ out)
{
    extern __shared__ float4 xs4[];   // [NTF][CHUNK/4] = [1024][8] float4
    const int tid = threadIdx.x;
    const int chunk = blockIdx.x & 3;       // 152 blocks -> 38 per chunk
    const int b0 = chunk * CHUNK;

    // ---- load feature slice: columns [b0, b0+32) of g_xT, transposed layout ----
    const float4* xg = (const float4*)g_xT;   // row stride = BATCH/4 = 32 float4
#pragma unroll 4
    for (int i = tid; i < NTF * (CHUNK / 4); i += THREADS) {
        const int row = i >> 3;
        const int c   = i & 7;
        xs4[i] = xg[row * (BATCH / 4) + chunk * (CHUNK / 4) + c];
    }

    __shared__ int s_tile;
    const int warp = tid >> 5;
    const int lane = tid & 31;
    const int gl   = lane >> 3;     // gene index within warp group (0..3)
    const int bsub = lane & 7;      // batch octet (0..7) -> batch b0 + bsub*4 .. +3

    for (;;) {
        __syncthreads();
        if (tid == 0) s_tile = (int)atomicAdd(&g_ticket[chunk], 1u);
        __syncthreads();
        const int tile = s_tile;
        if (tile >= NTILES) break;

        const int g = tile * GENES_PER_TILE + warp * 4 + gl;
        if (g >= NGENES) continue;   // all threads still reach loop-top barrier

        // ---------------- layer 1: 4 nodes x 16 edges ----------------
        float4 h1[4];
        const float4 b1v = *(const float4*)(b1 + g * 4);
#pragma unroll
        for (int n = 0; n < 4; n++) {
            const int eoff = (g * 4 + n) * 16;
            const int4*   ip = (const int4*)(in1 + eoff);
            const float4* wp = (const float4*)(w1 + eoff);
            float4 acc = make_float4(0.f, 0.f, 0.f, 0.f);
#pragma unroll
            for (int q = 0; q < 4; q++) {
                const int4   iv = __ldg(ip + q);
                const float4 wv = __ldg(wp + q);
                acc = fma4(wv.x, xs4[iv.x * 8 + bsub], acc);
                acc = fma4(wv.y, xs4[iv.y * 8 + bsub], acc);
                acc = fma4(wv.z, xs4[iv.z * 8 + bsub], acc);
                acc = fma4(wv.w, xs4[iv.w * 8 + bsub], acc);
            }
            h1[n] = tanh4(acc, comp(b1v, n));
        }

        // ---------------- layer 2: dense 4x4 per gene ----------------
        float4 h2[4];
        const float4 b2v = *(const float4*)(b2 + g * 4);
#pragma unroll
        for (int o = 0; o < 4; o++) {
            const float4 w2v = __ldg((const float4*)(w2 + g * 16 + o * 4));
            float4 s = make_float4(0.f, 0.f, 0.f, 0.f);
            s = fma4(w2v.x, h1[0], s);
            s = fma4(w2v.y, h1[1], s);
            s = fma4(w2v.z, h1[2], s);
            s = fma4(w2v.w, h1[3], s);
            h2[o] = tanh4(s, comp(b2v, o));
        }

        // ---------------- layer 3: 4 -> 1 per gene ----------------
        const float4 w3v = __ldg((const float4*)(w3 + g * 4));
        const float  b3v = __ldg(b3 + g);
        float4 y = make_float4(b3v, b3v, b3v, b3v);
        y = fma4(w3v.x, h2[0], y);
        y = fma4(w3v.y, h2[1], y);
        y = fma4(w3v.z, h2[2], y);
        y = fma4(w3v.w, h2[3], y);

        const int brow = b0 + bsub * 4;
        out[(long)(brow + 0) * NGENES + g] = y.x;
        out[(long)(brow + 1) * NGENES + g] = y.y;
        out[(long)(brow + 2) * NGENES + g] = y.z;
        out[(long)(brow + 3) * NGENES + g] = y.w;
    }
}

extern "C" void kernel_launch(void* const* d_in, const int* in_sizes, int n_in,
                              void* d_out, int out_size) {
    const float* features = (const float*)d_in[0];
    const float* w1 = (const float*)d_in[1];
    const float* b1 = (const float*)d_in[2];
    const float* w2 = (const float*)d_in[3];
    const float* b2 = (const float*)d_in[4];
    const float* w3 = (const float*)d_in[5];
    const float* b3 = (const float*)d_in[6];
    // d_in[7] = out1 (implied by structure), d_in[8] = in1 (random TF gather)
    const int* in1 = (const int*)d_in[8];
    float* out = (float*)d_out;

    cudaFuncSetAttribute(fused_kernel,
                         cudaFuncAttributeMaxDynamicSharedMemorySize, SMEM_BYTES);

    dim3 tb(32, 8);
    dim3 tg(NTF / 32, BATCH / 32);
    transpose_kernel<<<tg, tb>>>(features);
    fused_kernel<<<152, THREADS, SMEM_BYTES>>>(w1, b1, w2, b2, w3, b3, in1, out);
}

// round 2
// speedup vs baseline: 1.1777x; 1.1777x over previous
#include <cuda_runtime.h>

#define BATCH 128
#define NTF 1024
#define NGENES 20000
#define NQUADS (NGENES / 4)      // 5000 gene-quads
#define CHUNK 32                 // batch elements per block (feature slice in smem)
#define NCHUNK 4                 // 128 / 32
#define THREADS 512              // 16 warps
#define BLOCKS_PER_CHUNK 38
#define WARPS_PER_CHUNK (BLOCKS_PER_CHUNK * 16)   // 608
#define SMEM_BYTES (NTF * CHUNK * 4)  // 131072

// scratch: transposed features [NTF][BATCH]
__device__ float g_xT[NTF * BATCH];

// features [BATCH][NTF] -> g_xT [NTF][BATCH]
__global__ void transpose_kernel(const float* __restrict__ f) {
    __shared__ float tile[32][33];
    const int tx = threadIdx.x, ty = threadIdx.y;
    const int t0 = blockIdx.x * 32;   // TF base
    const int b0 = blockIdx.y * 32;   // batch base
#pragma unroll
    for (int j = 0; j < 32; j += 8)
        tile[ty + j][tx] = f[(b0 + ty + j) * NTF + t0 + tx];
    __syncthreads();
#pragma unroll
    for (int j = 0; j < 32; j += 8)
        g_xT[(t0 + ty + j) * BATCH + b0 + tx] = tile[tx][ty + j];
}

__device__ __forceinline__ float4 fma4(float s, float4 f, float4 a) {
    a.x += s * f.x; a.y += s * f.y; a.z += s * f.z; a.w += s * f.w;
    return a;
}

__device__ __forceinline__ float4 tanh4(float4 a, float b) {
    return make_float4(tanhf(a.x + b), tanhf(a.y + b),
                       tanhf(a.z + b), tanhf(a.w + b));
}

__device__ __forceinline__ float comp(float4 v, int i) {
    return (i == 0) ? v.x : (i == 1) ? v.y : (i == 2) ? v.z : v.w;
}

__global__ void __launch_bounds__(THREADS, 1) fused_kernel(
    const float* __restrict__ w1, const float* __restrict__ b1,
    const float* __restrict__ w2, const float* __restrict__ b2,
    const float* __restrict__ w3, const float* __restrict__ b3,
    const int*   __restrict__ in1,
    float* __restrict__ out)
{
    extern __shared__ float4 xs4[];   // [NTF][CHUNK/4] = [1024][8] float4
    const int tid = threadIdx.x;
    const int chunk = blockIdx.x & 3;            // 152 blocks -> 38 per chunk
    const int bg    = blockIdx.x >> 2;           // 0..37 within chunk
    const int b0 = chunk * CHUNK;

    // ---- load feature slice: columns [b0, b0+32) of g_xT ----
    const float4* xg = (const float4*)g_xT;   // row stride = BATCH/4 = 32 float4
#pragma unroll 4
    for (int i = tid; i < NTF * (CHUNK / 4); i += THREADS) {
        const int row = i >> 3;
        const int c   = i & 7;
        xs4[i] = xg[row * (BATCH / 4) + chunk * (CHUNK / 4) + c];
    }
    __syncthreads();

    const int warp = tid >> 5;
    const int lane = tid & 31;
    const int gl   = lane >> 3;     // gene index within quad (0..3)
    const int bsub = lane & 7;      // batch octet -> batch b0 + bsub*4 .. +3
    const int wg   = bg * 16 + warp;             // 0..607 warp id within chunk

    // static strided quad assignment: no atomics, no barriers in main loop
    for (int quad = wg; quad < NQUADS; quad += WARPS_PER_CHUNK) {
        const int g = quad * 4 + gl;

        // ---------------- layer 1: 4 nodes x 16 edges, software pipelined ----
        float4 h1[4];
        const float4 b1v = __ldg((const float4*)(b1 + g * 4));

        int4   ibuf[2][4];
        float4 wbuf[2][4];
        {
            const int eoff0 = g * 64;
            const int4*   ip = (const int4*)(in1 + eoff0);
            const float4* wp = (const float4*)(w1 + eoff0);
#pragma unroll
            for (int q = 0; q < 4; q++) { ibuf[0][q] = __ldg(ip + q); wbuf[0][q] = __ldg(wp + q); }
        }

#pragma unroll
        for (int n = 0; n < 4; n++) {
            const int cur = n & 1;
            // prefetch next node's edges before computing this node
            if (n < 3) {
                const int eoff = g * 64 + (n + 1) * 16;
                const int4*   ip = (const int4*)(in1 + eoff);
                const float4* wp = (const float4*)(w1 + eoff);
#pragma unroll
                for (int q = 0; q < 4; q++) {
                    ibuf[cur ^ 1][q] = __ldg(ip + q);
                    wbuf[cur ^ 1][q] = __ldg(wp + q);
                }
            }
            float4 acc = make_float4(0.f, 0.f, 0.f, 0.f);
#pragma unroll
            for (int q = 0; q < 4; q++) {
                const int4   iv = ibuf[cur][q];
                const float4 wv = wbuf[cur][q];
                // issue all 4 LDS before consuming (MLP on shared loads)
                const float4 f0 = xs4[iv.x * 8 + bsub];
                const float4 f1 = xs4[iv.y * 8 + bsub];
                const float4 f2 = xs4[iv.z * 8 + bsub];
                const float4 f3 = xs4[iv.w * 8 + bsub];
                acc = fma4(wv.x, f0, acc);
                acc = fma4(wv.y, f1, acc);
                acc = fma4(wv.z, f2, acc);
                acc = fma4(wv.w, f3, acc);
            }
            h1[n] = tanh4(acc, comp(b1v, n));
        }

        // ---------------- layer 2: dense 4x4 per gene ----------------
        float4 h2[4];
        const float4 b2v = __ldg((const float4*)(b2 + g * 4));
#pragma unroll
        for (int o = 0; o < 4; o++) {
            const float4 w2v = __ldg((const float4*)(w2 + g * 16 + o * 4));
            float4 s = make_float4(0.f, 0.f, 0.f, 0.f);
            s = fma4(w2v.x, h1[0], s);
            s = fma4(w2v.y, h1[1], s);
            s = fma4(w2v.z, h1[2], s);
            s = fma4(w2v.w, h1[3], s);
            h2[o] = tanh4(s, comp(b2v, o));
        }

        // ---------------- layer 3: 4 -> 1 per gene ----------------
        const float4 w3v = __ldg((const float4*)(w3 + g * 4));
        const float  b3v = __ldg(b3 + g);
        float4 y = make_float4(b3v, b3v, b3v, b3v);
        y = fma4(w3v.x, h2[0], y);
        y = fma4(w3v.y, h2[1], y);
        y = fma4(w3v.z, h2[2], y);
        y = fma4(w3v.w, h2[3], y);

        const int brow = b0 + bsub * 4;
        out[(long)(brow + 0) * NGENES + g] = y.x;
        out[(long)(brow + 1) * NGENES + g] = y.y;
        out[(long)(brow + 2) * NGENES + g] = y.z;
        out[(long)(brow + 3) * NGENES + g] = y.w;
    }
}

extern "C" void kernel_launch(void* const* d_in, const int* in_sizes, int n_in,
                              void* d_out, int out_size) {
    const float* features = (const float*)d_in[0];
    const float* w1 = (const float*)d_in[1];
    const float* b1 = (const float*)d_in[2];
    const float* w2 = (const float*)d_in[3];
    const float* b2 = (const float*)d_in[4];
    const float* w3 = (const float*)d_in[5];
    const float* b3 = (const float*)d_in[6];
    const int* in1 = (const int*)d_in[8];
    float* out = (float*)d_out;

    cudaFuncSetAttribute(fused_kernel,
                         cudaFuncAttributeMaxDynamicSharedMemorySize, SMEM_BYTES);

    dim3 tb(32, 8);
    dim3 tg(NTF / 32, BATCH / 32);
    transpose_kernel<<<tg, tb>>>(features);
    fused_kernel<<<152, THREADS, SMEM_BYTES>>>(w1, b1, w2, b2, w3, b3, in1, out);
}

// round 3
// speedup vs baseline: 1.1950x; 1.0147x over previous
#include <cuda_runtime.h>

#define BATCH 128
#define NTF 1024
#define NGENES 20000
#define NQUADS (NGENES / 4)      // 5000 gene-quads
#define CHUNK 32                 // batch elements per block (feature slice in smem)
#define NCHUNK 4                 // 128 / 32
#define THREADS 1024             // 32 warps -> 64 regs/thread budget
#define GRID 148                 // one wave, 37 blocks per chunk
#define SMEM_BYTES (NTF * CHUNK * 4)  // 131072

// scratch: transposed features [NTF][BATCH] + per-chunk warp tickets
__device__ float g_xT[NTF * BATCH];
__device__ unsigned int g_ticket[NCHUNK];

// features [BATCH][NTF] -> g_xT [NTF][BATCH]; also reset tickets
__global__ void transpose_kernel(const float* __restrict__ f) {
    __shared__ float tile[32][33];
    const int tx = threadIdx.x, ty = threadIdx.y;
    const int t0 = blockIdx.x * 32;   // TF base
    const int b0 = blockIdx.y * 32;   // batch base
#pragma unroll
    for (int j = 0; j < 32; j += 8)
        tile[ty + j][tx] = f[(b0 + ty + j) * NTF + t0 + tx];
    __syncthreads();
#pragma unroll
    for (int j = 0; j < 32; j += 8)
        g_xT[(t0 + ty + j) * BATCH + b0 + tx] = tile[tx][ty + j];
    if (blockIdx.x == 0 && blockIdx.y == 0 && ty == 0 && tx < NCHUNK)
        g_ticket[tx] = 0u;
}

__device__ __forceinline__ float4 fma4(float s, float4 f, float4 a) {
    a.x += s * f.x; a.y += s * f.y; a.z += s * f.z; a.w += s * f.w;
    return a;
}

// fast accurate tanh: clamp + expf + fast divide (rel err ~2e-6)
__device__ __forceinline__ float tanh_fast(float x) {
    x = fminf(fmaxf(x, -15.f), 15.f);
    const float t = __expf(2.f * x);
    return __fdividef(t - 1.f, t + 1.f);
}

__device__ __forceinline__ float4 tanh4(float4 a, float b) {
    return make_float4(tanh_fast(a.x + b), tanh_fast(a.y + b),
                       tanh_fast(a.z + b), tanh_fast(a.w + b));
}

__device__ __forceinline__ float comp(float4 v, int i) {
    return (i == 0) ? v.x : (i == 1) ? v.y : (i == 2) ? v.z : v.w;
}

__global__ void __launch_bounds__(THREADS, 1) fused_kernel(
    const float* __restrict__ w1, const float* __restrict__ b1,
    const float* __restrict__ w2, const float* __restrict__ b2,
    const float* __restrict__ w3, const float* __restrict__ b3,
    const int*   __restrict__ in1,
    float* __restrict__ out)
{
    extern __shared__ float4 xs4[];   // [NTF][CHUNK/4] = [1024][8] float4
    const int tid = threadIdx.x;
    const int chunk = blockIdx.x & 3;            // 148 blocks -> 37 per chunk
    const int b0 = chunk * CHUNK;

    // ---- load feature slice: columns [b0, b0+32) of g_xT ----
    const float4* xg = (const float4*)g_xT;   // row stride = BATCH/4 = 32 float4
#pragma unroll 2
    for (int i = tid; i < NTF * (CHUNK / 4); i += THREADS) {
        const int row = i >> 3;
        const int c   = i & 7;
        xs4[i] = xg[row * (BATCH / 4) + chunk * (CHUNK / 4) + c];
    }
    __syncthreads();

    const int lane = tid & 31;
    const int gl   = lane >> 3;     // gene index within quad (0..3)
    const int bsub = lane & 7;      // batch octet -> batch b0 + bsub*4 .. +3

    // warp-granular dynamic work: no barriers, near-perfect balance
    for (;;) {
        int quad = 0;
        if (lane == 0) quad = (int)atomicAdd(&g_ticket[chunk], 1u);
        quad = __shfl_sync(0xffffffffu, quad, 0);
        if (quad >= NQUADS) break;

        const int g = quad * 4 + gl;

        // ---------------- layer 1: 4 nodes x 16 edges ----------------
        float4 h1[4];
        const float4 b1v = __ldg((const float4*)(b1 + g * 4));
#pragma unroll
        for (int n = 0; n < 4; n++) {
            const int eoff = (g * 4 + n) * 16;
            const int4*   ip = (const int4*)(in1 + eoff);
            const float4* wp = (const float4*)(w1 + eoff);
            float4 acc = make_float4(0.f, 0.f, 0.f, 0.f);
#pragma unroll
            for (int q = 0; q < 4; q++) {
                const int4   iv = __ldg(ip + q);
                const float4 wv = __ldg(wp + q);
                const float4 f0 = xs4[iv.x * 8 + bsub];
                const float4 f1 = xs4[iv.y * 8 + bsub];
                const float4 f2 = xs4[iv.z * 8 + bsub];
                const float4 f3 = xs4[iv.w * 8 + bsub];
                acc = fma4(wv.x, f0, acc);
                acc = fma4(wv.y, f1, acc);
                acc = fma4(wv.z, f2, acc);
                acc = fma4(wv.w, f3, acc);
            }
            h1[n] = tanh4(acc, comp(b1v, n));
        }

        // ------------- layers 2+3 fused (no h2 array) -------------
        const float4 b2v = __ldg((const float4*)(b2 + g * 4));
        const float4 w3v = __ldg((const float4*)(w3 + g * 4));
        const float  b3v = __ldg(b3 + g);
        float4 y = make_float4(b3v, b3v, b3v, b3v);
#pragma unroll
        for (int o = 0; o < 4; o++) {
            const float4 w2v = __ldg((const float4*)(w2 + g * 16 + o * 4));
            float4 s = make_float4(0.f, 0.f, 0.f, 0.f);
            s = fma4(w2v.x, h1[0], s);
            s = fma4(w2v.y, h1[1], s);
            s = fma4(w2v.z, h1[2], s);
            s = fma4(w2v.w, h1[3], s);
            const float4 t = tanh4(s, comp(b2v, o));
            y = fma4(comp(w3v, o), t, y);
        }

        const int brow = b0 + bsub * 4;
        out[(long)(brow + 0) * NGENES + g] = y.x;
        out[(long)(brow + 1) * NGENES + g] = y.y;
        out[(long)(brow + 2) * NGENES + g] = y.z;
        out[(long)(brow + 3) * NGENES + g] = y.w;
    }
}

extern "C" void kernel_launch(void* const* d_in, const int* in_sizes, int n_in,
                              void* d_out, int out_size) {
    const float* features = (const float*)d_in[0];
    const float* w1 = (const float*)d_in[1];
    const float* b1 = (const float*)d_in[2];
    const float* w2 = (const float*)d_in[3];
    const float* b2 = (const float*)d_in[4];
    const float* w3 = (const float*)d_in[5];
    const float* b3 = (const float*)d_in[6];
    const int* in1 = (const int*)d_in[8];
    float* out = (float*)d_out;

    cudaFuncSetAttribute(fused_kernel,
                         cudaFuncAttributeMaxDynamicSharedMemorySize, SMEM_BYTES);

    dim3 tb(32, 8);
    dim3 tg(NTF / 32, BATCH / 32);
    transpose_kernel<<<tg, tb>>>(features);
    fused_kernel<<<GRID, THREADS, SMEM_BYTES>>>(w1, b1, w2, b2, w3, b3, in1, out);
}

// round 4
// speedup vs baseline: 1.3182x; 1.1031x over previous
#include <cuda_runtime.h>
#include <cuda_fp16.h>

#define BATCH 128
#define NTF 1024
#define NGENES 20000
#define NPAIRS (NGENES / 2)      // 10000 gene-pairs
#define CHUNK 64                 // batch elements per block (fp16 row = 128B)
#define NCHUNK 2                 // 128 / 64
#define THREADS 1024             // 32 warps
#define GRID 148                 // one wave, 74 blocks per chunk
#define SMEM_BYTES (NTF * CHUNK * 2)  // 131072

// scratch: fp16 transposed features [NTF][BATCH], gene-major output, tickets
__device__ __half g_xTh[NTF * BATCH];
__device__ float  g_yT[NGENES * BATCH];
__device__ unsigned int g_ticket[NCHUNK];

// features [BATCH][NTF] -> g_xTh [NTF][BATCH] (fp16); reset tickets
__global__ void transpose_features(const float* __restrict__ f) {
    __shared__ float tile[32][33];
    const int tx = threadIdx.x, ty = threadIdx.y;
    const int t0 = blockIdx.x * 32;
    const int b0 = blockIdx.y * 32;
#pragma unroll
    for (int j = 0; j < 32; j += 8)
        tile[ty + j][tx] = f[(b0 + ty + j) * NTF + t0 + tx];
    __syncthreads();
#pragma unroll
    for (int j = 0; j < 32; j += 8)
        g_xTh[(t0 + ty + j) * BATCH + b0 + tx] = __float2half(tile[tx][ty + j]);
    if (blockIdx.x == 0 && blockIdx.y == 0 && ty == 0 && tx < NCHUNK)
        g_ticket[tx] = 0u;
}

// g_yT [NGENES][BATCH] -> out [BATCH][NGENES]
__global__ void transpose_out(float* __restrict__ out) {
    __shared__ float tile[32][33];
    const int tx = threadIdx.x, ty = threadIdx.y;
    const int g0 = blockIdx.x * 32;
    const int b0 = blockIdx.y * 32;
#pragma unroll
    for (int j = 0; j < 32; j += 8)
        tile[ty + j][tx] = g_yT[(g0 + ty + j) * BATCH + b0 + tx];
    __syncthreads();
#pragma unroll
    for (int j = 0; j < 32; j += 8)
        out[(b0 + ty + j) * NGENES + g0 + tx] = tile[tx][ty + j];
}

__device__ __forceinline__ float4 fma4(float s, float4 f, float4 a) {
    a.x += s * f.x; a.y += s * f.y; a.z += s * f.z; a.w += s * f.w;
    return a;
}

// 4 halves (as uint2) -> float4
__device__ __forceinline__ float4 h4f(uint2 r) {
    const float2 lo = __half22float2(*reinterpret_cast<__half2*>(&r.x));
    const float2 hi = __half22float2(*reinterpret_cast<__half2*>(&r.y));
    return make_float4(lo.x, lo.y, hi.x, hi.y);
}

// tanh = 1 - 2/(exp(2x)+1); pre-activations are O(10) max so no clamp needed
__device__ __forceinline__ float tanh_fast(float x) {
    const float t = __expf(2.f * x);
    const float r = __fdividef(1.f, t + 1.f);
    return fmaf(-2.f, r, 1.f);
}

__device__ __forceinline__ float4 tanh4(float4 a) {
    return make_float4(tanh_fast(a.x), tanh_fast(a.y),
                       tanh_fast(a.z), tanh_fast(a.w));
}

__device__ __forceinline__ float comp(float4 v, int i) {
    return (i == 0) ? v.x : (i == 1) ? v.y : (i == 2) ? v.z : v.w;
}

__device__ __forceinline__ float4 bcast4(float b) {
    return make_float4(b, b, b, b);
}

__global__ void __launch_bounds__(THREADS, 1) fused_kernel(
    const float* __restrict__ w1, const float* __restrict__ b1,
    const float* __restrict__ w2, const float* __restrict__ b2,
    const float* __restrict__ w3, const float* __restrict__ b3,
    const int*   __restrict__ in1)
{
    extern __shared__ uint2 xs2[];   // [NTF][16] uint2 -> 128B fp16 rows
    const int tid = threadIdx.x;
    const int chunk = blockIdx.x & 1;            // 148 blocks -> 74 per chunk
    const int b0 = chunk * CHUNK;

    // ---- fill feature slice: 64 fp16 batch-columns per TF row ----
    {
        const uint4* src = (const uint4*)g_xTh;  // global row = 16 uint4
        uint4* dst = (uint4*)xs2;                // smem row = 8 uint4
#pragma unroll
        for (int i = tid; i < NTF * 8; i += THREADS) {
            const int t = i >> 3, c = i & 7;
            dst[i] = src[t * 16 + chunk * 8 + c];
        }
    }
    __syncthreads();

    const int lane = tid & 31;
    const int gl   = lane >> 4;     // gene within pair (0..1)
    const int bsub = lane & 15;     // batch quad (0..15) -> b0 + bsub*4 .. +3

    for (;;) {
        int pair = 0;
        if (lane == 0) pair = (int)atomicAdd(&g_ticket[chunk], 1u);
        pair = __shfl_sync(0xffffffffu, pair, 0);
        if (pair >= NPAIRS) break;

        const int g = pair * 2 + gl;

        // ---------------- layer 1: 4 nodes x 16 edges ----------------
        float4 h1[4];
        const float4 b1v = __ldg((const float4*)(b1 + g * 4));
#pragma unroll
        for (int n = 0; n < 4; n++) {
            const int eoff = (g * 4 + n) * 16;
            const int4*   ip = (const int4*)(in1 + eoff);
            const float4* wp = (const float4*)(w1 + eoff);
            float4 acc = bcast4(comp(b1v, n));   // bias folded into init
#pragma unroll
            for (int q = 0; q < 4; q++) {
                const int4   iv = __ldg(ip + q);
                const float4 wv = __ldg(wp + q);
                const uint2 r0 = xs2[iv.x * 16 + bsub];
                const uint2 r1 = xs2[iv.y * 16 + bsub];
                const uint2 r2 = xs2[iv.z * 16 + bsub];
                const uint2 r3 = xs2[iv.w * 16 + bsub];
                acc = fma4(wv.x, h4f(r0), acc);
                acc = fma4(wv.y, h4f(r1), acc);
                acc = fma4(wv.z, h4f(r2), acc);
                acc = fma4(wv.w, h4f(r3), acc);
            }
            h1[n] = tanh4(acc);
        }

        // ------------- layers 2+3 fused (no h2 array) -------------
        const float4 b2v = __ldg((const float4*)(b2 + g * 4));
        const float4 w3v = __ldg((const float4*)(w3 + g * 4));
        const float  b3v = __ldg(b3 + g);
        float4 y = bcast4(b3v);
#pragma unroll
        for (int o = 0; o < 4; o++) {
            const float4 w2v = __ldg((const float4*)(w2 + g * 16 + o * 4));
            float4 s = bcast4(comp(b2v, o));
            s = fma4(w2v.x, h1[0], s);
            s = fma4(w2v.y, h1[1], s);
            s = fma4(w2v.z, h1[2], s);
            s = fma4(w2v.w, h1[3], s);
            y = fma4(comp(w3v, o), tanh4(s), y);
        }

        // coalesced gene-major store (float4 per lane)
        *(float4*)&g_yT[g * BATCH + b0 + bsub * 4] = y;
    }
}

extern "C" void kernel_launch(void* const* d_in, const int* in_sizes, int n_in,
                              void* d_out, int out_size) {
    const float* features = (const float*)d_in[0];
    const float* w1 = (const float*)d_in[1];
    const float* b1 = (const float*)d_in[2];
    const float* w2 = (const float*)d_in[3];
    const float* b2 = (const float*)d_in[4];
    const float* w3 = (const float*)d_in[5];
    const float* b3 = (const float*)d_in[6];
    const int* in1 = (const int*)d_in[8];
    float* out = (float*)d_out;

    cudaFuncSetAttribute(fused_kernel,
                         cudaFuncAttributeMaxDynamicSharedMemorySize, SMEM_BYTES);

    dim3 tb(32, 8);
    transpose_features<<<dim3(NTF / 32, BATCH / 32), tb>>>(features);
    fused_kernel<<<GRID, THREADS, SMEM_BYTES>>>(w1, b1, w2, b2, w3, b3, in1);
    transpose_out<<<dim3(NGENES / 32, BATCH / 32), tb>>>(out);
}

// round 5
// speedup vs baseline: 1.3193x; 1.0008x over previous
#include <cuda_runtime.h>
#include <cuda_fp16.h>

#define BATCH 128
#define NTF 1024
#define NGENES 20000
#define NPAIRS (NGENES / 2)      // 10000 gene-pairs
#define NEDGE1 (NGENES * 4 * 16) // 1,280,000 layer-1 edges
#define CHUNK 64                 // batch elements per block (fp16 row = 128B)
#define NCHUNK 2                 // 128 / 64
#define THREADS 1024             // 32 warps
#define GRID 148                 // one wave, 74 blocks per chunk
#define SMEM_BYTES (NTF * CHUNK * 2)  // 131072

// scratch: fp16 transposed features, duplicated fp16 weights, gene-major out, tickets
__device__ __half  g_xTh[NTF * BATCH];
__device__ __half2 g_w1d[NEDGE1];
__device__ float   g_yT[NGENES * BATCH];
__device__ unsigned int g_ticket[NCHUNK];

// one prep kernel: feature transpose->fp16, w1 fp32 -> half2(w,w), ticket reset
// blocks [0,128): transpose tiles; blocks [128,288): weight conversion
__global__ void prep_kernel(const float* __restrict__ f,
                            const float* __restrict__ w1) {
    if (blockIdx.x < 128) {
        __shared__ float tile[32][33];
        const int tx = threadIdx.x & 31, ty = threadIdx.x >> 5;
        const int bx = blockIdx.x & 31, by = blockIdx.x >> 5;
        const int t0 = bx * 32;   // TF base
        const int b0 = by * 32;   // batch base
#pragma unroll
        for (int j = 0; j < 32; j += 8)
            tile[ty + j][tx] = f[(b0 + ty + j) * NTF + t0 + tx];
        __syncthreads();
#pragma unroll
        for (int j = 0; j < 32; j += 8)
            g_xTh[(t0 + ty + j) * BATCH + b0 + tx] = __float2half(tile[tx][ty + j]);
        if (blockIdx.x == 0 && threadIdx.x < NCHUNK)
            g_ticket[threadIdx.x] = 0u;
    } else {
        // 160 blocks x 256 threads x 32 elems = 1,310,720 >= NEDGE1
        const int base = (blockIdx.x - 128) * (256 * 32) + threadIdx.x;
#pragma unroll 8
        for (int k = 0; k < 32; k++) {
            const int e = base + k * 256;
            if (e < NEDGE1) {
                const __half h = __float2half(w1[e]);
                g_w1d[e] = __halves2half2(h, h);
            }
        }
    }
}

// g_yT [NGENES][BATCH] -> out [BATCH][NGENES]
__global__ void transpose_out(float* __restrict__ out) {
    __shared__ float tile[32][33];
    const int tx = threadIdx.x, ty = threadIdx.y;
    const int g0 = blockIdx.x * 32;
    const int b0 = blockIdx.y * 32;
#pragma unroll
    for (int j = 0; j < 32; j += 8)
        tile[ty + j][tx] = g_yT[(g0 + ty + j) * BATCH + b0 + tx];
    __syncthreads();
#pragma unroll
    for (int j = 0; j < 32; j += 8)
        out[(b0 + ty + j) * NGENES + g0 + tx] = tile[tx][ty + j];
}

__device__ __forceinline__ float4 fma4(float s, float4 f, float4 a) {
    a.x += s * f.x; a.y += s * f.y; a.z += s * f.z; a.w += s * f.w;
    return a;
}

// tanh = 1 - 2/(exp(2x)+1); pre-activations bounded, no clamp needed
__device__ __forceinline__ float tanh_fast(float x) {
    const float t = __expf(2.f * x);
    const float r = __fdividef(1.f, t + 1.f);
    return fmaf(-2.f, r, 1.f);
}

__device__ __forceinline__ float4 tanh4(float4 a) {
    return make_float4(tanh_fast(a.x), tanh_fast(a.y),
                       tanh_fast(a.z), tanh_fast(a.w));
}

__device__ __forceinline__ float comp(float4 v, int i) {
    return (i == 0) ? v.x : (i == 1) ? v.y : (i == 2) ? v.z : v.w;
}

__device__ __forceinline__ float4 bcast4(float b) {
    return make_float4(b, b, b, b);
}

__device__ __forceinline__ __half2 u2h(unsigned int u) {
    return *reinterpret_cast<__half2*>(&u);
}

__global__ void __launch_bounds__(THREADS, 1) fused_kernel(
    const float* __restrict__ b1,
    const float* __restrict__ w2, const float* __restrict__ b2,
    const float* __restrict__ w3, const float* __restrict__ b3,
    const int*   __restrict__ in1)
{
    extern __shared__ uint2 xs2[];   // [NTF][16] uint2 -> 128B fp16 rows
    const int tid = threadIdx.x;
    const int chunk = blockIdx.x & 1;            // 148 blocks -> 74 per chunk
    const int b0 = chunk * CHUNK;

    // ---- fill feature slice: 64 fp16 batch-columns per TF row ----
    {
        const uint4* src = (const uint4*)g_xTh;  // global row = 16 uint4
        uint4* dst = (uint4*)xs2;                // smem row = 8 uint4
#pragma unroll
        for (int i = tid; i < NTF * 8; i += THREADS) {
            const int t = i >> 3, c = i & 7;
            dst[i] = src[t * 16 + chunk * 8 + c];
        }
    }
    __syncthreads();

    const int lane = tid & 31;
    const int gl   = lane >> 4;     // gene within pair (0..1)
    const int bsub = lane & 15;     // batch quad (0..15) -> b0 + bsub*4 .. +3

    for (;;) {
        int pair = 0;
        if (lane == 0) pair = (int)atomicAdd(&g_ticket[chunk], 1u);
        pair = __shfl_sync(0xffffffffu, pair, 0);
        if (pair >= NPAIRS) break;

        const int g = pair * 2 + gl;

        // ---------------- layer 1: 4 nodes x 16 edges, HFMA2 groups of 4 ----
        float4 h1[4];
        const float4 b1v = __ldg((const float4*)(b1 + g * 4));
#pragma unroll
        for (int n = 0; n < 4; n++) {
            const int eoff = (g * 4 + n) * 16;
            const int4*  ip = (const int4*)(in1 + eoff);
            const uint4* wp = (const uint4*)(g_w1d + eoff);  // 4 half2 per uint4
            float4 acc = bcast4(comp(b1v, n));   // fp32 master accumulator
#pragma unroll
            for (int q = 0; q < 4; q++) {
                const int4  iv = __ldg(ip + q);
                const uint4 wv = __ldg(wp + q);
                const uint2 r0 = xs2[iv.x * 16 + bsub];
                const uint2 r1 = xs2[iv.y * 16 + bsub];
                const uint2 r2 = xs2[iv.z * 16 + bsub];
                const uint2 r3 = xs2[iv.w * 16 + bsub];
                // fp16 partial over 4 edges (batches 0-1 in lo, 2-3 in hi)
                __half2 alo = __hmul2(u2h(wv.x), u2h(r0.x));
                __half2 ahi = __hmul2(u2h(wv.x), u2h(r0.y));
                alo = __hfma2(u2h(wv.y), u2h(r1.x), alo);
                ahi = __hfma2(u2h(wv.y), u2h(r1.y), ahi);
                alo = __hfma2(u2h(wv.z), u2h(r2.x), alo);
                ahi = __hfma2(u2h(wv.z), u2h(r2.y), ahi);
                alo = __hfma2(u2h(wv.w), u2h(r3.x), alo);
                ahi = __hfma2(u2h(wv.w), u2h(r3.y), ahi);
                const float2 flo = __half22float2(alo);
                const float2 fhi = __half22float2(ahi);
                acc.x += flo.x; acc.y += flo.y;
                acc.z += fhi.x; acc.w += fhi.y;
            }
            h1[n] = tanh4(acc);
        }

        // ------------- layers 2+3 fused (fp32) -------------
        const float4 b2v = __ldg((const float4*)(b2 + g * 4));
        const float4 w3v = __ldg((const float4*)(w3 + g * 4));
        const float  b3v = __ldg(b3 + g);
        float4 y = bcast4(b3v);
#pragma unroll
        for (int o = 0; o < 4; o++) {
            const float4 w2v = __ldg((const float4*)(w2 + g * 16 + o * 4));
            float4 s = bcast4(comp(b2v, o));
            s = fma4(w2v.x, h1[0], s);
            s = fma4(w2v.y, h1[1], s);
            s = fma4(w2v.z, h1[2], s);
            s = fma4(w2v.w, h1[3], s);
            y = fma4(comp(w3v, o), tanh4(s), y);
        }

        // coalesced gene-major store (float4 per lane)
        *(float4*)&g_yT[g * BATCH + b0 + bsub * 4] = y;
    }
}

extern "C" void kernel_launch(void* const* d_in, const int* in_sizes, int n_in,
                              void* d_out, int out_size) {
    const float* features = (const float*)d_in[0];
    const float* w1 = (const float*)d_in[1];
    const float* b1 = (const float*)d_in[2];
    const float* w2 = (const float*)d_in[3];
    const float* b2 = (const float*)d_in[4];
    const float* w3 = (const float*)d_in[5];
    const float* b3 = (const float*)d_in[6];
    const int* in1 = (const int*)d_in[8];
    float* out = (float*)d_out;

    cudaFuncSetAttribute(fused_kernel,
                         cudaFuncAttributeMaxDynamicSharedMemorySize, SMEM_BYTES);

    prep_kernel<<<288, 256>>>(features, w1);
    fused_kernel<<<GRID, THREADS, SMEM_BYTES>>>(b1, w2, b2, w3, b3, in1);
    transpose_out<<<dim3(NGENES / 32, BATCH / 32), dim3(32, 8)>>>(out);
}

// round 6
// speedup vs baseline: 1.5615x; 1.1837x over previous
#include <cuda_runtime.h>
#include <cuda_fp16.h>

#define BATCH 128
#define NTF 1024
#define NGENES 20000
#define NPAIRS (NGENES / 2)      // 10000 gene-pairs
#define NEDGE1 (NGENES * 4 * 16) // 1,280,000 layer-1 edges
#define CHUNK 64                 // batch elements per block (fp16 row = 128B)
#define NCHUNK 2                 // 128 / 64
#define THREADS 1024             // 32 warps
#define GRID 148                 // one wave, 74 blocks per chunk
#define SMEM_BYTES (NTF * CHUNK * 2)  // 131072
#define WCONV_BLOCKS 625         // 625*256*8 = 1,280,000 = NEDGE1

// scratch: fp16 transposed features, fp16 weights, gene-major out, tickets
__device__ __half g_xTh[NTF * BATCH];
__device__ __half g_w1h[NEDGE1];
__device__ float  g_yT[NGENES * BATCH];
__device__ unsigned int g_ticket[NCHUNK];

__device__ __forceinline__ unsigned int packh2(float a, float b) {
    const __half2 h = __float22half2_rn(make_float2(a, b));
    return *reinterpret_cast<const unsigned int*>(&h);
}

// prep: blocks [0,128) transpose features->fp16 (+ticket reset);
//       blocks [128,128+625) convert w1 fp32->fp16, 8 edges/thread
__global__ void prep_kernel(const float* __restrict__ f,
                            const float* __restrict__ w1) {
    if (blockIdx.x < 128) {
        __shared__ float tile[32][33];
        const int tx = threadIdx.x & 31, ty = threadIdx.x >> 5;
        const int t0 = (blockIdx.x & 31) * 32;   // TF base
        const int b0 = (blockIdx.x >> 5) * 32;   // batch base
#pragma unroll
        for (int j = 0; j < 32; j += 8)
            tile[ty + j][tx] = f[(b0 + ty + j) * NTF + t0 + tx];
        __syncthreads();
#pragma unroll
        for (int j = 0; j < 32; j += 8)
            g_xTh[(t0 + ty + j) * BATCH + b0 + tx] = __float2half(tile[tx][ty + j]);
        if (blockIdx.x == 0 && threadIdx.x < NCHUNK)
            g_ticket[threadIdx.x] = 0u;
    } else {
        const int e = ((blockIdx.x - 128) * 256 + threadIdx.x) * 8;
        if (e < NEDGE1) {
            const float4 a = __ldg((const float4*)(w1 + e));
            const float4 b = __ldg((const float4*)(w1 + e) + 1);
            uint4 o;
            o.x = packh2(a.x, a.y);
            o.y = packh2(a.z, a.w);
            o.z = packh2(b.x, b.y);
            o.w = packh2(b.z, b.w);
            *(uint4*)(g_w1h + e) = o;
        }
    }
}

// g_yT [NGENES][BATCH] -> out [BATCH][NGENES]
__global__ void transpose_out(float* __restrict__ out) {
    __shared__ float tile[32][33];
    const int tx = threadIdx.x, ty = threadIdx.y;
    const int g0 = blockIdx.x * 32;
    const int b0 = blockIdx.y * 32;
#pragma unroll
    for (int j = 0; j < 32; j += 8)
        tile[ty + j][tx] = g_yT[(g0 + ty + j) * BATCH + b0 + tx];
    __syncthreads();
#pragma unroll
    for (int j = 0; j < 32; j += 8)
        out[(b0 + ty + j) * NGENES + g0 + tx] = tile[tx][ty + j];
}

__device__ __forceinline__ float4 fma4(float s, float4 f, float4 a) {
    a.x += s * f.x; a.y += s * f.y; a.z += s * f.z; a.w += s * f.w;
    return a;
}

// single-instruction tanh on the MUFU pipe
__device__ __forceinline__ float tanh_mufu(float x) {
    float y;
    asm("tanh.approx.f32 %0, %1;" : "=f"(y) : "f"(x));
    return y;
}

__device__ __forceinline__ float4 tanh4(float4 a) {
    return make_float4(tanh_mufu(a.x), tanh_mufu(a.y),
                       tanh_mufu(a.z), tanh_mufu(a.w));
}

__device__ __forceinline__ float comp(float4 v, int i) {
    return (i == 0) ? v.x : (i == 1) ? v.y : (i == 2) ? v.z : v.w;
}

__device__ __forceinline__ float4 bcast4(float b) {
    return make_float4(b, b, b, b);
}

__device__ __forceinline__ __half2 u2h(unsigned int u) {
    return *reinterpret_cast<__half2*>(&u);
}

__global__ void __launch_bounds__(THREADS, 1) fused_kernel(
    const float* __restrict__ b1,
    const float* __restrict__ w2, const float* __restrict__ b2,
    const float* __restrict__ w3, const float* __restrict__ b3,
    const int*   __restrict__ in1)
{
    extern __shared__ uint2 xs2[];   // [NTF][16] uint2 -> 128B fp16 rows
    const int tid = threadIdx.x;
    const int chunk = blockIdx.x & 1;            // 148 blocks -> 74 per chunk
    const int b0 = chunk * CHUNK;

    // ---- fill feature slice: 64 fp16 batch-columns per TF row ----
    {
        const uint4* src = (const uint4*)g_xTh;  // global row = 16 uint4
        uint4* dst = (uint4*)xs2;                // smem row = 8 uint4
#pragma unroll
        for (int i = tid; i < NTF * 8; i += THREADS) {
            const int t = i >> 3, c = i & 7;
            dst[i] = src[t * 16 + chunk * 8 + c];
        }
    }
    __syncthreads();

    const int lane = tid & 31;
    const int gl   = lane >> 4;     // gene within pair (0..1)
    const int bsub = lane & 15;     // batch quad (0..15) -> b0 + bsub*4 .. +3

    for (;;) {
        int pair = 0;
        if (lane == 0) pair = (int)atomicAdd(&g_ticket[chunk], 1u);
        pair = __shfl_sync(0xffffffffu, pair, 0);
        if (pair >= NPAIRS) break;

        const int g = pair * 2 + gl;

        // -------- layer 1: 4 nodes x 16 edges, HFMA2 + half selectors --------
        float4 h1[4];
        const float4 b1v = __ldg((const float4*)(b1 + g * 4));
#pragma unroll
        for (int n = 0; n < 4; n++) {
            const int eoff = (g * 4 + n) * 16;
            const int4*  ip = (const int4*)(in1 + eoff);
            const uint2* wp = (const uint2*)(g_w1h + eoff);  // 4 halves / uint2
            float4 acc = bcast4(comp(b1v, n));   // fp32 master accumulator
#pragma unroll
            for (int q = 0; q < 4; q++) {
                const int4  iv = __ldg(ip + q);
                const uint2 wv = __ldg(wp + q);
                const __half2 wx = u2h(wv.x), wy = u2h(wv.y);
                const uint2 r0 = xs2[iv.x * 16 + bsub];
                const uint2 r1 = xs2[iv.y * 16 + bsub];
                const uint2 r2 = xs2[iv.z * 16 + bsub];
                const uint2 r3 = xs2[iv.w * 16 + bsub];
                // fp16 partial over 4 edges; weight pair via .H0_H0/.H1_H1
                __half2 alo = __hmul2(__low2half2(wx),  u2h(r0.x));
                __half2 ahi = __hmul2(__low2half2(wx),  u2h(r0.y));
                alo = __hfma2(__high2half2(wx), u2h(r1.x), alo);
                ahi = __hfma2(__high2half2(wx), u2h(r1.y), ahi);
                alo = __hfma2(__low2half2(wy),  u2h(r2.x), alo);
                ahi = __hfma2(__low2half2(wy),  u2h(r2.y), ahi);
                alo = __hfma2(__high2half2(wy), u2h(r3.x), alo);
                ahi = __hfma2(__high2half2(wy), u2h(r3.y), ahi);
                const float2 flo = __half22float2(alo);
                const float2 fhi = __half22float2(ahi);
                acc.x += flo.x; acc.y += flo.y;
                acc.z += fhi.x; acc.w += fhi.y;
            }
            h1[n] = tanh4(acc);
        }

        // ------------- layers 2+3 fused (fp32, MUFU tanh) -------------
        const float4 b2v = __ldg((const float4*)(b2 + g * 4));
        const float4 w3v = __ldg((const float4*)(w3 + g * 4));
        const float  b3v = __ldg(b3 + g);
        float4 y = bcast4(b3v);
#pragma unroll
        for (int o = 0; o < 4; o++) {
            const float4 w2v = __ldg((const float4*)(w2 + g * 16 + o * 4));
            float4 s = bcast4(comp(b2v, o));
            s = fma4(w2v.x, h1[0], s);
            s = fma4(w2v.y, h1[1], s);
            s = fma4(w2v.z, h1[2], s);
            s = fma4(w2v.w, h1[3], s);
            y = fma4(comp(w3v, o), tanh4(s), y);
        }

        // coalesced gene-major store (float4 per lane)
        *(float4*)&g_yT[g * BATCH + b0 + bsub * 4] = y;
    }
}

extern "C" void kernel_launch(void* const* d_in, const int* in_sizes, int n_in,
                              void* d_out, int out_size) {
    const float* features = (const float*)d_in[0];
    const float* w1 = (const float*)d_in[1];
    const float* b1 = (const float*)d_in[2];
    const float* w2 = (const float*)d_in[3];
    const float* b2 = (const float*)d_in[4];
    const float* w3 = (const float*)d_in[5];
    const float* b3 = (const float*)d_in[6];
    const int* in1 = (const int*)d_in[8];
    float* out = (float*)d_out;

    cudaFuncSetAttribute(fused_kernel,
                         cudaFuncAttributeMaxDynamicSharedMemorySize, SMEM_BYTES);

    prep_kernel<<<128 + WCONV_BLOCKS, 256>>>(features, w1);
    fused_kernel<<<GRID, THREADS, SMEM_BYTES>>>(b1, w2, b2, w3, b3, in1);
    transpose_out<<<dim3(NGENES / 32, BATCH / 32), dim3(32, 8)>>>(out);
}